// round 1
// baseline (speedup 1.0000x reference)
#include <cuda_runtime.h>
#include <math.h>

// ---------------------------------------------------------------------------
// TemporalWormhole: 7-band windowed attention + cross-band gating. fp32.
// Shapes: B=8, T=1024, D=256. Tokens per band M = 8192.
// ---------------------------------------------------------------------------

#define D_DIM   256
#define M_ROWS  8192                      // B*T
#define SLAB    (M_ROWS * D_DIM)          // elements per band slab

// Scratch (device globals; no runtime allocation allowed)
__device__ float g_q[7 * SLAB];
__device__ float g_k[7 * SLAB];
__device__ float g_v[7 * SLAB];
__device__ float g_ctx[7 * SLAB];
__device__ float g_u[7 * SLAB];
__device__ float g_other[SLAB];

__constant__ int c_win[7] = {128, 64, 32, 16, 16, 8, 4};

struct BandPtrs { const float* p[7]; };

// ---------------------------------------------------------------------------
// Generic tile config: BM=64, BN=64, BK=16, 256 threads, 4x4 per thread.
// C[m,e] = sum_k A[m,k] * W[e,k] + bias[e]   (torch Linear, W row-major [N,K])
// ---------------------------------------------------------------------------

#define TB 256

__device__ __forceinline__ void sgemm_body_k256(
    const float* __restrict__ A, const float* __restrict__ W,
    const float* __restrict__ bias, float* __restrict__ C)
{
    __shared__ float As[16][65];
    __shared__ float Ws[16][65];
    const int tid = threadIdx.x;
    const int tx = tid & 15;          // 0..15 -> N micro
    const int ty = tid >> 4;          // 0..15 -> M micro
    const int row0 = blockIdx.x * 64;
    const int col0 = blockIdx.y * 64;

    float acc[4][4];
#pragma unroll
    for (int i = 0; i < 4; i++)
#pragma unroll
        for (int j = 0; j < 4; j++) acc[i][j] = 0.f;

    for (int k0 = 0; k0 < 256; k0 += 16) {
#pragma unroll
        for (int i = 0; i < 4; i++) {
            int idx = tid + i * TB;
            int r = idx >> 4, c = idx & 15;
            As[c][r] = A[(size_t)(row0 + r) * 256 + k0 + c];
        }
#pragma unroll
        for (int i = 0; i < 4; i++) {
            int idx = tid + i * TB;
            int r = idx >> 4, c = idx & 15;
            Ws[c][r] = W[(size_t)(col0 + r) * 256 + k0 + c];
        }
        __syncthreads();
#pragma unroll
        for (int kk = 0; kk < 16; kk++) {
            float a[4], b[4];
#pragma unroll
            for (int i = 0; i < 4; i++) a[i] = As[kk][ty * 4 + i];
#pragma unroll
            for (int j = 0; j < 4; j++) b[j] = Ws[kk][tx * 4 + j];
#pragma unroll
            for (int i = 0; i < 4; i++)
#pragma unroll
                for (int j = 0; j < 4; j++) acc[i][j] += a[i] * b[j];
        }
        __syncthreads();
    }

#pragma unroll
    for (int i = 0; i < 4; i++) {
        int m = row0 + ty * 4 + i;
#pragma unroll
        for (int j = 0; j < 4; j++) {
            int e = col0 + tx * 4 + j;
            C[(size_t)m * 256 + e] = acc[i][j] + bias[e];
        }
    }
}

// ---------------- K1: QKV projections (z = band*3 + {q,k,v}) ----------------
__global__ void qkv_gemm(BandPtrs bp,
                         const float* __restrict__ qw, const float* __restrict__ qb,
                         const float* __restrict__ kw, const float* __restrict__ kb,
                         const float* __restrict__ vw, const float* __restrict__ vb)
{
    int z = blockIdx.z;
    int n = z / 3, which = z - 3 * n;
    const float* A = bp.p[n];
    const float* W; const float* bias; float* C;
    if (which == 0)      { W = qw + (size_t)n * 65536; bias = qb + n * 256; C = g_q + (size_t)n * SLAB; }
    else if (which == 1) { W = kw + (size_t)n * 65536; bias = kb + n * 256; C = g_k + (size_t)n * SLAB; }
    else                 { W = vw + (size_t)n * 65536; bias = vb + n * 256; C = g_v + (size_t)n * SLAB; }
    sgemm_body_k256(A, W, bias, C);
}

// ---------------- K2: windowed attention, warp per query --------------------
__global__ void attn_kernel()
{
    int warp = (blockIdx.x * blockDim.x + threadIdx.x) >> 5;
    int lane = threadIdx.x & 31;
    if (warp >= 7 * M_ROWS) return;
    int n  = warp / M_ROWS;
    int tf = warp - n * M_ROWS;          // b*1024 + t
    int b  = tf >> 10;
    int t  = tf & 1023;
    int w  = c_win[n];

    const float* qrow = g_q + ((size_t)n * M_ROWS + tf) * 256;
    float qr[8];
#pragma unroll
    for (int c = 0; c < 8; c++) qr[c] = qrow[c * 32 + lane];

    int j0 = t - w + 1; if (j0 < 0) j0 = 0;
    int cnt = t - j0 + 1;                 // 1..128

    const float* kbase = g_k + ((size_t)n * M_ROWS + b * 1024) * 256;
    float sc[4];

    for (int jj = 0; jj < cnt; jj++) {
        const float* kr = kbase + (size_t)(j0 + jj) * 256;
        float p = 0.f;
#pragma unroll
        for (int c = 0; c < 8; c++) p += qr[c] * kr[c * 32 + lane];
#pragma unroll
        for (int off = 16; off > 0; off >>= 1)
            p += __shfl_xor_sync(0xffffffffu, p, off);
        if ((jj & 31) == lane) sc[jj >> 5] = p;
    }

    const float scale = 0.0625f;          // 1/sqrt(256)
    float mx = -1e30f;
#pragma unroll
    for (int s = 0; s < 4; s++) {
        int jj = s * 32 + lane;
        if (jj < cnt) mx = fmaxf(mx, sc[s] * scale);
    }
#pragma unroll
    for (int off = 16; off > 0; off >>= 1)
        mx = fmaxf(mx, __shfl_xor_sync(0xffffffffu, mx, off));

    float sum = 0.f;
#pragma unroll
    for (int s = 0; s < 4; s++) {
        int jj = s * 32 + lane;
        float e = (jj < cnt) ? expf(sc[s] * scale - mx) : 0.f;
        sc[s] = e;
        sum += e;
    }
#pragma unroll
    for (int off = 16; off > 0; off >>= 1)
        sum += __shfl_xor_sync(0xffffffffu, sum, off);
    float inv = 1.f / sum;

    float acc[8];
#pragma unroll
    for (int c = 0; c < 8; c++) acc[c] = 0.f;
    const float* vbase = g_v + ((size_t)n * M_ROWS + b * 1024) * 256;
    for (int jj = 0; jj < cnt; jj++) {
        float p = __shfl_sync(0xffffffffu, sc[jj >> 5], jj & 31);
        const float* vr = vbase + (size_t)(j0 + jj) * 256;
#pragma unroll
        for (int c = 0; c < 8; c++) acc[c] += p * vr[c * 32 + lane];
    }

    float* crow = g_ctx + ((size_t)n * M_ROWS + tf) * 256;
#pragma unroll
    for (int c = 0; c < 8; c++) crow[c * 32 + lane] = acc[c] * inv;
}

// ---------------- K3: other = mean of ctx over bands != 3 -------------------
__global__ void other_kernel()
{
    int i = blockIdx.x * blockDim.x + threadIdx.x;
    if (i >= SLAB) return;
    float s = 0.f;
#pragma unroll
    for (int nn = 0; nn < 7; nn++)
        if (nn != 3) s += g_ctx[(size_t)nn * SLAB + i];
    g_other[i] = s * (1.f / 6.f);
}

// ---------------- K4: per-band update projections u[n] ----------------------
// PAIRS=((0,6),(1,5),(2,4)): u[high]=ctx[low]@crossw[p]^T+crossb[p],
//                            u[low] =ctx[high]@crossrw[p]^T+crossrb[p],
//                            u[3]   =other@bridgew^T+bridgeb
__global__ void u_gemm(const float* __restrict__ crossw,  const float* __restrict__ crossb,
                       const float* __restrict__ crossrw, const float* __restrict__ crossrb,
                       const float* __restrict__ bridgew, const float* __restrict__ bridgeb)
{
    int n = blockIdx.z;
    const float *A, *W, *bias;
    switch (n) {
        case 0:  A = g_ctx + (size_t)6 * SLAB; W = crossrw;             bias = crossrb;       break;
        case 1:  A = g_ctx + (size_t)5 * SLAB; W = crossrw + 65536;     bias = crossrb + 256; break;
        case 2:  A = g_ctx + (size_t)4 * SLAB; W = crossrw + 2 * 65536; bias = crossrb + 512; break;
        case 3:  A = g_other;                  W = bridgew;             bias = bridgeb;       break;
        case 4:  A = g_ctx + (size_t)2 * SLAB; W = crossw + 2 * 65536;  bias = crossb + 512;  break;
        case 5:  A = g_ctx + (size_t)1 * SLAB; W = crossw + 65536;      bias = crossb + 256;  break;
        default: A = g_ctx;                    W = crossw;              bias = crossb;        break;
    }
    float* C = g_u + (size_t)n * SLAB;
    sgemm_body_k256(A, W, bias, C);
}

// ---------------- K5: gate GEMM (K=512 concat) + sigmoid + residual ---------
// out[n] = band[n] + sigmoid( [band[n], u[n]] @ gatew[n]^T + gateb[n] ) * u[n]
__global__ void gate_gemm(BandPtrs bp, const float* __restrict__ gatew,
                          const float* __restrict__ gateb, float* __restrict__ out)
{
    int n = blockIdx.z;
    const float* X = bp.p[n];
    const float* U = g_u + (size_t)n * SLAB;
    const float* W = gatew + (size_t)n * 256 * 512;
    const float* bias = gateb + n * 256;
    float* C = out + (size_t)n * SLAB;

    __shared__ float As[16][65];
    __shared__ float Ws[16][65];
    const int tid = threadIdx.x;
    const int tx = tid & 15;
    const int ty = tid >> 4;
    const int row0 = blockIdx.x * 64;
    const int col0 = blockIdx.y * 64;

    float acc[4][4];
#pragma unroll
    for (int i = 0; i < 4; i++)
#pragma unroll
        for (int j = 0; j < 4; j++) acc[i][j] = 0.f;

    for (int k0 = 0; k0 < 512; k0 += 16) {
#pragma unroll
        for (int i = 0; i < 4; i++) {
            int idx = tid + i * TB;
            int r = idx >> 4, c = idx & 15;
            int kg = k0 + c;
            float v = (kg < 256) ? X[(size_t)(row0 + r) * 256 + kg]
                                 : U[(size_t)(row0 + r) * 256 + (kg - 256)];
            As[c][r] = v;
        }
#pragma unroll
        for (int i = 0; i < 4; i++) {
            int idx = tid + i * TB;
            int r = idx >> 4, c = idx & 15;
            Ws[c][r] = W[(size_t)(col0 + r) * 512 + k0 + c];
        }
        __syncthreads();
#pragma unroll
        for (int kk = 0; kk < 16; kk++) {
            float a[4], b[4];
#pragma unroll
            for (int i = 0; i < 4; i++) a[i] = As[kk][ty * 4 + i];
#pragma unroll
            for (int j = 0; j < 4; j++) b[j] = Ws[kk][tx * 4 + j];
#pragma unroll
            for (int i = 0; i < 4; i++)
#pragma unroll
                for (int j = 0; j < 4; j++) acc[i][j] += a[i] * b[j];
        }
        __syncthreads();
    }

#pragma unroll
    for (int i = 0; i < 4; i++) {
        int m = row0 + ty * 4 + i;
#pragma unroll
        for (int j = 0; j < 4; j++) {
            int e = col0 + tx * 4 + j;
            float s = acc[i][j] + bias[e];
            float g = 1.f / (1.f + expf(-s));
            size_t off = (size_t)m * 256 + e;
            C[off] = X[off] + g * U[off];
        }
    }
}

// ---------------------------------------------------------------------------
extern "C" void kernel_launch(void* const* d_in, const int* in_sizes, int n_in,
                              void* d_out, int out_size)
{
    BandPtrs bp;
    for (int i = 0; i < 7; i++) bp.p[i] = (const float*)d_in[i];
    const float* qw      = (const float*)d_in[7];
    const float* qb      = (const float*)d_in[8];
    const float* kw      = (const float*)d_in[9];
    const float* kb      = (const float*)d_in[10];
    const float* vw      = (const float*)d_in[11];
    const float* vb      = (const float*)d_in[12];
    const float* crossw  = (const float*)d_in[13];
    const float* crossb  = (const float*)d_in[14];
    const float* crossrw = (const float*)d_in[15];
    const float* crossrb = (const float*)d_in[16];
    const float* gatew   = (const float*)d_in[17];
    const float* gateb   = (const float*)d_in[18];
    const float* bridgew = (const float*)d_in[19];
    const float* bridgeb = (const float*)d_in[20];
    float* out = (float*)d_out;

    // 1) QKV projections: 21 GEMMs of [8192,256]x[256,256]
    qkv_gemm<<<dim3(M_ROWS / 64, D_DIM / 64, 21), TB>>>(bp, qw, qb, kw, kb, vw, vb);

    // 2) Windowed attention: warp per query, 7*8192 queries, 8 warps/block
    attn_kernel<<<(7 * M_ROWS) / 8, 256>>>();

    // 3) other = mean of ctx over bands != 3
    other_kernel<<<SLAB / 256, 256>>>();

    // 4) update projections u[0..6]
    u_gemm<<<dim3(M_ROWS / 64, D_DIM / 64, 7), TB>>>(crossw, crossb, crossrw, crossrb,
                                                     bridgew, bridgeb);

    // 5) gate (K=512) + sigmoid + residual -> d_out
    gate_gemm<<<dim3(M_ROWS / 64, D_DIM / 64, 7), TB>>>(bp, gatew, gateb, out);
}

// round 2
// speedup vs baseline: 1.7680x; 1.7680x over previous
#include <cuda_runtime.h>
#include <math.h>

// ---------------------------------------------------------------------------
// TemporalWormhole: 7-band windowed attention + cross-band gating. fp32.
// B=8, T=1024, D=256. M = B*T = 8192 tokens per band.
// ---------------------------------------------------------------------------

#define D_DIM   256
#define M_ROWS  8192
#define SLAB    (M_ROWS * D_DIM)

__device__ float g_q[7 * SLAB];
__device__ float g_k[7 * SLAB];
__device__ float g_v[7 * SLAB];
__device__ float g_ctx[7 * SLAB];
__device__ float g_u[7 * SLAB];
__device__ float g_other[SLAB];

__constant__ int c_win[7] = {128, 64, 32, 16, 16, 8, 4};

struct BandPtrs { const float* p[7]; };

// ---------------------------------------------------------------------------
// SGEMM: 128x128 tile, BK=8, 256 threads, 8x8 per thread, float4 everywhere.
// C[m,e] = sum_k A[m,k] * W[e,k] + bias[e]   (torch Linear; W row-major [N,K])
// GATE variant: A is concat(X, U) along K (512), epilogue does
//   out = X + sigmoid(C) * U
// ---------------------------------------------------------------------------

template<bool GATE>
__device__ __forceinline__ void sgemm128_body(
    const float* __restrict__ AX,     // A for k in [0,256)
    const float* __restrict__ AU,     // A for k in [256,512) (GATE only)
    const float* __restrict__ W, int ldw,
    const float* __restrict__ bias,
    float* __restrict__ C)
{
    const int KDIM = GATE ? 512 : 256;
    __shared__ float As[8][128];
    __shared__ float Bs[8][128];

    const int tid  = threadIdx.x;
    const int arow = tid >> 1;            // 0..127
    const int acol = (tid & 1) * 4;       // 0 or 4
    const int tx   = tid & 15;            // N micro
    const int ty   = tid >> 4;            // M micro
    const int row0 = blockIdx.x * 128;
    const int col0 = blockIdx.y * 128;

    float acc[8][8];
#pragma unroll
    for (int i = 0; i < 8; i++)
#pragma unroll
        for (int j = 0; j < 8; j++) acc[i][j] = 0.f;

    // first tile -> smem
    {
        float4 a = *(const float4*)&AX[(size_t)(row0 + arow) * 256 + acol];
        float4 w = *(const float4*)&W[(size_t)(col0 + arow) * ldw + acol];
        As[acol + 0][arow] = a.x; As[acol + 1][arow] = a.y;
        As[acol + 2][arow] = a.z; As[acol + 3][arow] = a.w;
        Bs[acol + 0][arow] = w.x; Bs[acol + 1][arow] = w.y;
        Bs[acol + 2][arow] = w.z; Bs[acol + 3][arow] = w.w;
    }
    __syncthreads();

    for (int k0 = 0; k0 < KDIM; k0 += 8) {
        float4 an, wn;
        const bool has_next = (k0 + 8) < KDIM;
        if (has_next) {
            int kn = k0 + 8;
            const float* Abase; int kloc;
            if (GATE && kn >= 256) { Abase = AU; kloc = kn - 256; }
            else                   { Abase = AX; kloc = kn; }
            an = *(const float4*)&Abase[(size_t)(row0 + arow) * 256 + kloc + acol];
            wn = *(const float4*)&W[(size_t)(col0 + arow) * ldw + kn + acol];
        }
#pragma unroll
        for (int kk = 0; kk < 8; kk++) {
            float4 a0 = *(const float4*)&As[kk][ty * 8];
            float4 a1 = *(const float4*)&As[kk][ty * 8 + 4];
            float4 b0 = *(const float4*)&Bs[kk][tx * 8];
            float4 b1 = *(const float4*)&Bs[kk][tx * 8 + 4];
            float av[8] = {a0.x, a0.y, a0.z, a0.w, a1.x, a1.y, a1.z, a1.w};
            float bv[8] = {b0.x, b0.y, b0.z, b0.w, b1.x, b1.y, b1.z, b1.w};
#pragma unroll
            for (int i = 0; i < 8; i++)
#pragma unroll
                for (int j = 0; j < 8; j++) acc[i][j] += av[i] * bv[j];
        }
        __syncthreads();
        if (has_next) {
            As[acol + 0][arow] = an.x; As[acol + 1][arow] = an.y;
            As[acol + 2][arow] = an.z; As[acol + 3][arow] = an.w;
            Bs[acol + 0][arow] = wn.x; Bs[acol + 1][arow] = wn.y;
            Bs[acol + 2][arow] = wn.z; Bs[acol + 3][arow] = wn.w;
            __syncthreads();
        }
    }

    float bv[8];
#pragma unroll
    for (int j = 0; j < 8; j++) bv[j] = bias[col0 + tx * 8 + j];

#pragma unroll
    for (int i = 0; i < 8; i++) {
        int m = row0 + ty * 8 + i;
        size_t base = (size_t)m * 256 + col0 + tx * 8;
        if (!GATE) {
            float4 o0, o1;
            o0.x = acc[i][0] + bv[0]; o0.y = acc[i][1] + bv[1];
            o0.z = acc[i][2] + bv[2]; o0.w = acc[i][3] + bv[3];
            o1.x = acc[i][4] + bv[4]; o1.y = acc[i][5] + bv[5];
            o1.z = acc[i][6] + bv[6]; o1.w = acc[i][7] + bv[7];
            *(float4*)&C[base]     = o0;
            *(float4*)&C[base + 4] = o1;
        } else {
            float4 x0 = *(const float4*)&AX[base];
            float4 x1 = *(const float4*)&AX[base + 4];
            float4 u0 = *(const float4*)&AU[base];
            float4 u1 = *(const float4*)&AU[base + 4];
            float xv[8] = {x0.x, x0.y, x0.z, x0.w, x1.x, x1.y, x1.z, x1.w};
            float uv[8] = {u0.x, u0.y, u0.z, u0.w, u1.x, u1.y, u1.z, u1.w};
            float ov[8];
#pragma unroll
            for (int j = 0; j < 8; j++) {
                float s = acc[i][j] + bv[j];
                float g = 1.f / (1.f + expf(-s));
                ov[j] = xv[j] + g * uv[j];
            }
            float4 o0 = {ov[0], ov[1], ov[2], ov[3]};
            float4 o1 = {ov[4], ov[5], ov[6], ov[7]};
            *(float4*)&C[base]     = o0;
            *(float4*)&C[base + 4] = o1;
        }
    }
}

// ---------------- K1: QKV projections (z = band*3 + {q,k,v}) ----------------
__global__ void __launch_bounds__(256, 2)
qkv_gemm(BandPtrs bp,
         const float* __restrict__ qw, const float* __restrict__ qb,
         const float* __restrict__ kw, const float* __restrict__ kb,
         const float* __restrict__ vw, const float* __restrict__ vb)
{
    int z = blockIdx.z;
    int n = z / 3, which = z - 3 * n;
    const float* A = bp.p[n];
    const float* W; const float* bias; float* C;
    if (which == 0)      { W = qw + (size_t)n * 65536; bias = qb + n * 256; C = g_q + (size_t)n * SLAB; }
    else if (which == 1) { W = kw + (size_t)n * 65536; bias = kb + n * 256; C = g_k + (size_t)n * SLAB; }
    else                 { W = vw + (size_t)n * 65536; bias = vb + n * 256; C = g_v + (size_t)n * SLAB; }
    sgemm128_body<false>(A, nullptr, W, 256, bias, C);
}

// ---------------- K2: windowed attention, warp per query --------------------
__global__ void attn_kernel()
{
    int warp = (blockIdx.x * blockDim.x + threadIdx.x) >> 5;
    int lane = threadIdx.x & 31;
    if (warp >= 7 * M_ROWS) return;
    int n  = warp / M_ROWS;
    int tf = warp - n * M_ROWS;
    int b  = tf >> 10;
    int t  = tf & 1023;
    int w  = c_win[n];

    const float4* qrow = (const float4*)(g_q + ((size_t)n * M_ROWS + tf) * 256);
    float4 q0 = qrow[lane];
    float4 q1 = qrow[lane + 32];

    int j0 = t - w + 1; if (j0 < 0) j0 = 0;
    int cnt = t - j0 + 1;                 // 1..128

    const float4* kbase = (const float4*)(g_k + ((size_t)n * M_ROWS + (size_t)b * 1024 + j0) * 256);
    float sc[4];

    for (int jj = 0; jj < cnt; jj++) {
        const float4* kr = kbase + (size_t)jj * 64;
        float4 k0 = kr[lane];
        float4 k1 = kr[lane + 32];
        float p = q0.x * k0.x + q0.y * k0.y + q0.z * k0.z + q0.w * k0.w
                + q1.x * k1.x + q1.y * k1.y + q1.z * k1.z + q1.w * k1.w;
#pragma unroll
        for (int off = 16; off > 0; off >>= 1)
            p += __shfl_xor_sync(0xffffffffu, p, off);
        if ((jj & 31) == lane) sc[jj >> 5] = p;
    }

    const float scale = 0.0625f;
    float mx = -1e30f;
#pragma unroll
    for (int s = 0; s < 4; s++) {
        int jj = s * 32 + lane;
        if (jj < cnt) mx = fmaxf(mx, sc[s] * scale);
    }
#pragma unroll
    for (int off = 16; off > 0; off >>= 1)
        mx = fmaxf(mx, __shfl_xor_sync(0xffffffffu, mx, off));

    float sum = 0.f;
#pragma unroll
    for (int s = 0; s < 4; s++) {
        int jj = s * 32 + lane;
        float e = (jj < cnt) ? expf(sc[s] * scale - mx) : 0.f;
        sc[s] = e;
        sum += e;
    }
#pragma unroll
    for (int off = 16; off > 0; off >>= 1)
        sum += __shfl_xor_sync(0xffffffffu, sum, off);
    float inv = 1.f / sum;

    float4 acc0 = {0.f, 0.f, 0.f, 0.f};
    float4 acc1 = {0.f, 0.f, 0.f, 0.f};
    const float4* vbase = (const float4*)(g_v + ((size_t)n * M_ROWS + (size_t)b * 1024 + j0) * 256);
    for (int jj = 0; jj < cnt; jj++) {
        float p = __shfl_sync(0xffffffffu, sc[jj >> 5], jj & 31);
        const float4* vr = vbase + (size_t)jj * 64;
        float4 v0 = vr[lane];
        float4 v1 = vr[lane + 32];
        acc0.x += p * v0.x; acc0.y += p * v0.y; acc0.z += p * v0.z; acc0.w += p * v0.w;
        acc1.x += p * v1.x; acc1.y += p * v1.y; acc1.z += p * v1.z; acc1.w += p * v1.w;
    }

    float4* crow = (float4*)(g_ctx + ((size_t)n * M_ROWS + tf) * 256);
    acc0.x *= inv; acc0.y *= inv; acc0.z *= inv; acc0.w *= inv;
    acc1.x *= inv; acc1.y *= inv; acc1.z *= inv; acc1.w *= inv;
    crow[lane]      = acc0;
    crow[lane + 32] = acc1;
}

// ---------------- K3: other = mean of ctx over bands != 3 -------------------
__global__ void other_kernel()
{
    int i = blockIdx.x * blockDim.x + threadIdx.x;   // float4 index
    if (i >= SLAB / 4) return;
    const float4* c = (const float4*)g_ctx;
    float4 s = {0.f, 0.f, 0.f, 0.f};
#pragma unroll
    for (int nn = 0; nn < 7; nn++) {
        if (nn == 3) continue;
        float4 v = c[(size_t)nn * (SLAB / 4) + i];
        s.x += v.x; s.y += v.y; s.z += v.z; s.w += v.w;
    }
    const float k = 1.f / 6.f;
    s.x *= k; s.y *= k; s.z *= k; s.w *= k;
    ((float4*)g_other)[i] = s;
}

// ---------------- K4: per-band update projections u[n] ----------------------
__global__ void __launch_bounds__(256, 2)
u_gemm(const float* __restrict__ crossw,  const float* __restrict__ crossb,
       const float* __restrict__ crossrw, const float* __restrict__ crossrb,
       const float* __restrict__ bridgew, const float* __restrict__ bridgeb)
{
    int n = blockIdx.z;
    const float *A, *W, *bias;
    switch (n) {
        case 0:  A = g_ctx + (size_t)6 * SLAB; W = crossrw;             bias = crossrb;       break;
        case 1:  A = g_ctx + (size_t)5 * SLAB; W = crossrw + 65536;     bias = crossrb + 256; break;
        case 2:  A = g_ctx + (size_t)4 * SLAB; W = crossrw + 2 * 65536; bias = crossrb + 512; break;
        case 3:  A = g_other;                  W = bridgew;             bias = bridgeb;       break;
        case 4:  A = g_ctx + (size_t)2 * SLAB; W = crossw + 2 * 65536;  bias = crossb + 512;  break;
        case 5:  A = g_ctx + (size_t)1 * SLAB; W = crossw + 65536;      bias = crossb + 256;  break;
        default: A = g_ctx;                    W = crossw;              bias = crossb;        break;
    }
    sgemm128_body<false>(A, nullptr, W, 256, bias, g_u + (size_t)n * SLAB);
}

// ---------------- K5: gate GEMM (K=512 concat) + sigmoid + residual ---------
__global__ void __launch_bounds__(256, 2)
gate_gemm(BandPtrs bp, const float* __restrict__ gatew,
          const float* __restrict__ gateb, float* __restrict__ out)
{
    int n = blockIdx.z;
    const float* X = bp.p[n];
    const float* U = g_u + (size_t)n * SLAB;
    sgemm128_body<true>(X, U, gatew + (size_t)n * 256 * 512, 512,
                        gateb + n * 256, out + (size_t)n * SLAB);
}

// ---------------------------------------------------------------------------
extern "C" void kernel_launch(void* const* d_in, const int* in_sizes, int n_in,
                              void* d_out, int out_size)
{
    BandPtrs bp;
    for (int i = 0; i < 7; i++) bp.p[i] = (const float*)d_in[i];
    const float* qw      = (const float*)d_in[7];
    const float* qb      = (const float*)d_in[8];
    const float* kw      = (const float*)d_in[9];
    const float* kb      = (const float*)d_in[10];
    const float* vw      = (const float*)d_in[11];
    const float* vb      = (const float*)d_in[12];
    const float* crossw  = (const float*)d_in[13];
    const float* crossb  = (const float*)d_in[14];
    const float* crossrw = (const float*)d_in[15];
    const float* crossrb = (const float*)d_in[16];
    const float* gatew   = (const float*)d_in[17];
    const float* gateb   = (const float*)d_in[18];
    const float* bridgew = (const float*)d_in[19];
    const float* bridgeb = (const float*)d_in[20];
    float* out = (float*)d_out;

    qkv_gemm<<<dim3(M_ROWS / 128, D_DIM / 128, 21), 256>>>(bp, qw, qb, kw, kb, vw, vb);
    attn_kernel<<<(7 * M_ROWS) / 8, 256>>>();
    other_kernel<<<(SLAB / 4) / 256, 256>>>();
    u_gemm<<<dim3(M_ROWS / 128, D_DIM / 128, 7), 256>>>(crossw, crossb, crossrw, crossrb,
                                                        bridgew, bridgeb);
    gate_gemm<<<dim3(M_ROWS / 128, D_DIM / 128, 7), 256>>>(bp, gatew, gateb, out);
}

// round 3
// speedup vs baseline: 2.0773x; 1.1749x over previous
#include <cuda_runtime.h>
#include <math.h>

// ---------------------------------------------------------------------------
// TemporalWormhole: 7-band windowed attention + cross-band gating. fp32.
// B=8, T=1024, D=256. M = B*T = 8192 tokens per band.
// ---------------------------------------------------------------------------

#define D_DIM   256
#define M_ROWS  8192
#define SLAB    (M_ROWS * D_DIM)

__device__ float g_q[7 * SLAB];
__device__ float g_k[7 * SLAB];
__device__ float g_v[7 * SLAB];
__device__ float g_ctx[7 * SLAB];
__device__ float g_u[7 * SLAB];
__device__ float g_other[SLAB];

__constant__ int c_win[7] = {128, 64, 32, 16, 16, 8, 4};

struct BandPtrs { const float* p[7]; };

// ---------------------------------------------------------------------------
// SGEMM: 128x128 tile, BK=16, 256 threads, 8x8/thread in z-order (4+4 split),
// conflict-free LDS.128 fragment reads, 2-stage smem double buffer.
// C[m,e] = sum_k A[m,k] * W[e,k] + bias[e]   (torch Linear; W row-major [N,K])
// GATE: A = concat(X,U) along K (512); epilogue out = X + sigmoid(C)*U.
// ---------------------------------------------------------------------------

#define SROW 132   // padded row stride (floats); 132*4B = 16B-aligned, conflict-free reads

template<bool GATE>
__device__ __forceinline__ void sgemm128_body(
    const float* __restrict__ AX,
    const float* __restrict__ AU,
    const float* __restrict__ W, int ldw,
    const float* __restrict__ bias,
    float* __restrict__ C)
{
    const int NKT = GATE ? 32 : 16;           // number of BK=16 tiles
    __shared__ float As[2][16][SROW];
    __shared__ float Bs[2][16][SROW];

    const int tid  = threadIdx.x;
    const int tx   = tid & 15;
    const int ty   = tid >> 4;
    const int lm   = tid >> 2;                // 0..63 (row within half-tile)
    const int lk4  = tid & 3;                 // which k-float4 (covers k0..k15)
    const int row0 = blockIdx.x * 128;
    const int col0 = blockIdx.y * 128;

    float acc[8][8];
#pragma unroll
    for (int i = 0; i < 8; i++)
#pragma unroll
        for (int j = 0; j < 8; j++) acc[i][j] = 0.f;

    // ---- load tile 0 into stage 0 ----
    {
        const float* Ab = AX;
        float4 a0 = *(const float4*)&Ab[(size_t)(row0 + lm) * 256 + lk4 * 4];
        float4 a1 = *(const float4*)&Ab[(size_t)(row0 + lm + 64) * 256 + lk4 * 4];
        float4 w0 = *(const float4*)&W[(size_t)(col0 + lm) * ldw + lk4 * 4];
        float4 w1 = *(const float4*)&W[(size_t)(col0 + lm + 64) * ldw + lk4 * 4];
        int kb = lk4 * 4;
        As[0][kb + 0][lm] = a0.x; As[0][kb + 1][lm] = a0.y;
        As[0][kb + 2][lm] = a0.z; As[0][kb + 3][lm] = a0.w;
        As[0][kb + 0][lm + 64] = a1.x; As[0][kb + 1][lm + 64] = a1.y;
        As[0][kb + 2][lm + 64] = a1.z; As[0][kb + 3][lm + 64] = a1.w;
        Bs[0][kb + 0][lm] = w0.x; Bs[0][kb + 1][lm] = w0.y;
        Bs[0][kb + 2][lm] = w0.z; Bs[0][kb + 3][lm] = w0.w;
        Bs[0][kb + 0][lm + 64] = w1.x; Bs[0][kb + 1][lm + 64] = w1.y;
        Bs[0][kb + 2][lm + 64] = w1.z; Bs[0][kb + 3][lm + 64] = w1.w;
    }
    __syncthreads();

    for (int kt = 0; kt < NKT; kt++) {
        const int cs = kt & 1;
        float4 a0n, a1n, w0n, w1n;
        const bool has_next = (kt + 1) < NKT;
        if (has_next) {
            int kn = (kt + 1) * 16;
            const float* Ab; int kloc;
            if (GATE && kn >= 256) { Ab = AU; kloc = kn - 256; }
            else                   { Ab = AX; kloc = kn; }
            a0n = *(const float4*)&Ab[(size_t)(row0 + lm) * 256 + kloc + lk4 * 4];
            a1n = *(const float4*)&Ab[(size_t)(row0 + lm + 64) * 256 + kloc + lk4 * 4];
            w0n = *(const float4*)&W[(size_t)(col0 + lm) * ldw + kn + lk4 * 4];
            w1n = *(const float4*)&W[(size_t)(col0 + lm + 64) * ldw + kn + lk4 * 4];
        }

#pragma unroll
        for (int kk = 0; kk < 16; kk++) {
            float4 a0 = *(const float4*)&As[cs][kk][ty * 4];
            float4 a1 = *(const float4*)&As[cs][kk][64 + ty * 4];
            float4 b0 = *(const float4*)&Bs[cs][kk][tx * 4];
            float4 b1 = *(const float4*)&Bs[cs][kk][64 + tx * 4];
            float av[8] = {a0.x, a0.y, a0.z, a0.w, a1.x, a1.y, a1.z, a1.w};
            float bv[8] = {b0.x, b0.y, b0.z, b0.w, b1.x, b1.y, b1.z, b1.w};
#pragma unroll
            for (int i = 0; i < 8; i++)
#pragma unroll
                for (int j = 0; j < 8; j++) acc[i][j] += av[i] * bv[j];
        }

        if (has_next) {
            const int ns = cs ^ 1;
            int kb = lk4 * 4;
            As[ns][kb + 0][lm] = a0n.x; As[ns][kb + 1][lm] = a0n.y;
            As[ns][kb + 2][lm] = a0n.z; As[ns][kb + 3][lm] = a0n.w;
            As[ns][kb + 0][lm + 64] = a1n.x; As[ns][kb + 1][lm + 64] = a1n.y;
            As[ns][kb + 2][lm + 64] = a1n.z; As[ns][kb + 3][lm + 64] = a1n.w;
            Bs[ns][kb + 0][lm] = w0n.x; Bs[ns][kb + 1][lm] = w0n.y;
            Bs[ns][kb + 2][lm] = w0n.z; Bs[ns][kb + 3][lm] = w0n.w;
            Bs[ns][kb + 0][lm + 64] = w1n.x; Bs[ns][kb + 1][lm + 64] = w1n.y;
            Bs[ns][kb + 2][lm + 64] = w1n.z; Bs[ns][kb + 3][lm + 64] = w1n.w;
            __syncthreads();
        }
    }

    // ---- epilogue ----
    float bv[8];
#pragma unroll
    for (int j = 0; j < 8; j++) {
        int e = (j < 4) ? (col0 + tx * 4 + j) : (col0 + 64 + tx * 4 + j - 4);
        bv[j] = bias[e];
    }

#pragma unroll
    for (int i = 0; i < 8; i++) {
        int m = row0 + ((i < 4) ? (ty * 4 + i) : (64 + ty * 4 + i - 4));
        size_t b0 = (size_t)m * 256 + col0 + tx * 4;
        size_t b1 = (size_t)m * 256 + col0 + 64 + tx * 4;
        if (!GATE) {
            float4 o0 = {acc[i][0] + bv[0], acc[i][1] + bv[1],
                         acc[i][2] + bv[2], acc[i][3] + bv[3]};
            float4 o1 = {acc[i][4] + bv[4], acc[i][5] + bv[5],
                         acc[i][6] + bv[6], acc[i][7] + bv[7]};
            *(float4*)&C[b0] = o0;
            *(float4*)&C[b1] = o1;
        } else {
            float4 x0 = *(const float4*)&AX[b0];
            float4 x1 = *(const float4*)&AX[b1];
            float4 u0 = *(const float4*)&AU[b0];
            float4 u1 = *(const float4*)&AU[b1];
            float xv[8] = {x0.x, x0.y, x0.z, x0.w, x1.x, x1.y, x1.z, x1.w};
            float uv[8] = {u0.x, u0.y, u0.z, u0.w, u1.x, u1.y, u1.z, u1.w};
            float ov[8];
#pragma unroll
            for (int j = 0; j < 8; j++) {
                float s = acc[i][j] + bv[j];
                float g = 1.f / (1.f + __expf(-s));
                ov[j] = xv[j] + g * uv[j];
            }
            float4 o0 = {ov[0], ov[1], ov[2], ov[3]};
            float4 o1 = {ov[4], ov[5], ov[6], ov[7]};
            *(float4*)&C[b0] = o0;
            *(float4*)&C[b1] = o1;
        }
    }
}

// ---------------- K1: QKV projections (z = band*3 + {q,k,v}) ----------------
__global__ void __launch_bounds__(256, 2)
qkv_gemm(BandPtrs bp,
         const float* __restrict__ qw, const float* __restrict__ qb,
         const float* __restrict__ kw, const float* __restrict__ kb,
         const float* __restrict__ vw, const float* __restrict__ vb)
{
    int z = blockIdx.z;
    int n = z / 3, which = z - 3 * n;
    const float* A = bp.p[n];
    const float* W; const float* bias; float* C;
    if (which == 0)      { W = qw + (size_t)n * 65536; bias = qb + n * 256; C = g_q + (size_t)n * SLAB; }
    else if (which == 1) { W = kw + (size_t)n * 65536; bias = kb + n * 256; C = g_k + (size_t)n * SLAB; }
    else                 { W = vw + (size_t)n * 65536; bias = vb + n * 256; C = g_v + (size_t)n * SLAB; }
    sgemm128_body<false>(A, nullptr, W, 256, bias, C);
}

// ---------------- K2: windowed attention, warp per query --------------------
__global__ void attn_kernel()
{
    int warp = (blockIdx.x * blockDim.x + threadIdx.x) >> 5;
    int lane = threadIdx.x & 31;
    if (warp >= 7 * M_ROWS) return;
    int n  = warp / M_ROWS;
    int tf = warp - n * M_ROWS;
    int b  = tf >> 10;
    int t  = tf & 1023;
    int w  = c_win[n];

    const float4* qrow = (const float4*)(g_q + ((size_t)n * M_ROWS + tf) * 256);
    float4 q0 = qrow[lane];
    float4 q1 = qrow[lane + 32];

    int j0 = t - w + 1; if (j0 < 0) j0 = 0;
    int cnt = t - j0 + 1;                 // 1..128

    const float4* kbase = (const float4*)(g_k + ((size_t)n * M_ROWS + (size_t)b * 1024 + j0) * 256);
    float sc[4];

    for (int jj = 0; jj < cnt; jj++) {
        const float4* kr = kbase + (size_t)jj * 64;
        float4 k0 = kr[lane];
        float4 k1 = kr[lane + 32];
        float p = q0.x * k0.x + q0.y * k0.y + q0.z * k0.z + q0.w * k0.w
                + q1.x * k1.x + q1.y * k1.y + q1.z * k1.z + q1.w * k1.w;
#pragma unroll
        for (int off = 16; off > 0; off >>= 1)
            p += __shfl_xor_sync(0xffffffffu, p, off);
        if ((jj & 31) == lane) sc[jj >> 5] = p;
    }

    const float scale = 0.0625f;
    float mx = -1e30f;
#pragma unroll
    for (int s = 0; s < 4; s++) {
        int jj = s * 32 + lane;
        if (jj < cnt) mx = fmaxf(mx, sc[s] * scale);
    }
#pragma unroll
    for (int off = 16; off > 0; off >>= 1)
        mx = fmaxf(mx, __shfl_xor_sync(0xffffffffu, mx, off));

    float sum = 0.f;
#pragma unroll
    for (int s = 0; s < 4; s++) {
        int jj = s * 32 + lane;
        float e = (jj < cnt) ? expf(sc[s] * scale - mx) : 0.f;
        sc[s] = e;
        sum += e;
    }
#pragma unroll
    for (int off = 16; off > 0; off >>= 1)
        sum += __shfl_xor_sync(0xffffffffu, sum, off);
    float inv = 1.f / sum;

    float4 acc0 = {0.f, 0.f, 0.f, 0.f};
    float4 acc1 = {0.f, 0.f, 0.f, 0.f};
    const float4* vbase = (const float4*)(g_v + ((size_t)n * M_ROWS + (size_t)b * 1024 + j0) * 256);
    for (int jj = 0; jj < cnt; jj++) {
        float p = __shfl_sync(0xffffffffu, sc[jj >> 5], jj & 31);
        const float4* vr = vbase + (size_t)jj * 64;
        float4 v0 = vr[lane];
        float4 v1 = vr[lane + 32];
        acc0.x += p * v0.x; acc0.y += p * v0.y; acc0.z += p * v0.z; acc0.w += p * v0.w;
        acc1.x += p * v1.x; acc1.y += p * v1.y; acc1.z += p * v1.z; acc1.w += p * v1.w;
    }

    float4* crow = (float4*)(g_ctx + ((size_t)n * M_ROWS + tf) * 256);
    acc0.x *= inv; acc0.y *= inv; acc0.z *= inv; acc0.w *= inv;
    acc1.x *= inv; acc1.y *= inv; acc1.z *= inv; acc1.w *= inv;
    crow[lane]      = acc0;
    crow[lane + 32] = acc1;
}

// ---------------- K3: other = mean of ctx over bands != 3 -------------------
__global__ void other_kernel()
{
    int i = blockIdx.x * blockDim.x + threadIdx.x;   // float4 index
    if (i >= SLAB / 4) return;
    const float4* c = (const float4*)g_ctx;
    float4 s = {0.f, 0.f, 0.f, 0.f};
#pragma unroll
    for (int nn = 0; nn < 7; nn++) {
        if (nn == 3) continue;
        float4 v = c[(size_t)nn * (SLAB / 4) + i];
        s.x += v.x; s.y += v.y; s.z += v.z; s.w += v.w;
    }
    const float k = 1.f / 6.f;
    s.x *= k; s.y *= k; s.z *= k; s.w *= k;
    ((float4*)g_other)[i] = s;
}

// ---------------- K4: per-band update projections u[n] ----------------------
__global__ void __launch_bounds__(256, 2)
u_gemm(const float* __restrict__ crossw,  const float* __restrict__ crossb,
       const float* __restrict__ crossrw, const float* __restrict__ crossrb,
       const float* __restrict__ bridgew, const float* __restrict__ bridgeb)
{
    int n = blockIdx.z;
    const float *A, *W, *bias;
    switch (n) {
        case 0:  A = g_ctx + (size_t)6 * SLAB; W = crossrw;             bias = crossrb;       break;
        case 1:  A = g_ctx + (size_t)5 * SLAB; W = crossrw + 65536;     bias = crossrb + 256; break;
        case 2:  A = g_ctx + (size_t)4 * SLAB; W = crossrw + 2 * 65536; bias = crossrb + 512; break;
        case 3:  A = g_other;                  W = bridgew;             bias = bridgeb;       break;
        case 4:  A = g_ctx + (size_t)2 * SLAB; W = crossw + 2 * 65536;  bias = crossb + 512;  break;
        case 5:  A = g_ctx + (size_t)1 * SLAB; W = crossw + 65536;      bias = crossb + 256;  break;
        default: A = g_ctx;                    W = crossw;              bias = crossb;        break;
    }
    sgemm128_body<false>(A, nullptr, W, 256, bias, g_u + (size_t)n * SLAB);
}

// ---------------- K5: gate GEMM (K=512 concat) + sigmoid + residual ---------
__global__ void __launch_bounds__(256, 2)
gate_gemm(BandPtrs bp, const float* __restrict__ gatew,
          const float* __restrict__ gateb, float* __restrict__ out)
{
    int n = blockIdx.z;
    const float* X = bp.p[n];
    const float* U = g_u + (size_t)n * SLAB;
    sgemm128_body<true>(X, U, gatew + (size_t)n * 256 * 512, 512,
                        gateb + n * 256, out + (size_t)n * SLAB);
}

// ---------------------------------------------------------------------------
extern "C" void kernel_launch(void* const* d_in, const int* in_sizes, int n_in,
                              void* d_out, int out_size)
{
    BandPtrs bp;
    for (int i = 0; i < 7; i++) bp.p[i] = (const float*)d_in[i];
    const float* qw      = (const float*)d_in[7];
    const float* qb      = (const float*)d_in[8];
    const float* kw      = (const float*)d_in[9];
    const float* kb      = (const float*)d_in[10];
    const float* vw      = (const float*)d_in[11];
    const float* vb      = (const float*)d_in[12];
    const float* crossw  = (const float*)d_in[13];
    const float* crossb  = (const float*)d_in[14];
    const float* crossrw = (const float*)d_in[15];
    const float* crossrb = (const float*)d_in[16];
    const float* gatew   = (const float*)d_in[17];
    const float* gateb   = (const float*)d_in[18];
    const float* bridgew = (const float*)d_in[19];
    const float* bridgeb = (const float*)d_in[20];
    float* out = (float*)d_out;

    qkv_gemm<<<dim3(M_ROWS / 128, D_DIM / 128, 21), 256>>>(bp, qw, qb, kw, kb, vw, vb);
    attn_kernel<<<(7 * M_ROWS) / 8, 256>>>();
    other_kernel<<<(SLAB / 4) / 256, 256>>>();
    u_gemm<<<dim3(M_ROWS / 128, D_DIM / 128, 7), 256>>>(crossw, crossb, crossrw, crossrb,
                                                        bridgew, bridgeb);
    gate_gemm<<<dim3(M_ROWS / 128, D_DIM / 128, 7), 256>>>(bp, gatew, gateb, out);
}

// round 5
// speedup vs baseline: 3.2382x; 1.5589x over previous
#include <cuda_runtime.h>
#include <math.h>
#include <stdint.h>

// ---------------------------------------------------------------------------
// TemporalWormhole: tf32 mma.sync GEMMs + fp32 windowed attention.
// B=8, T=1024, D=256. M = B*T = 8192 tokens per band.
// (tcgen05 is unavailable: harness compiles for plain sm_103, no 'a' features.)
// ---------------------------------------------------------------------------

#define D_DIM   256
#define M_ROWS  8192
#define SLAB    (M_ROWS * D_DIM)

__device__ float g_q[7 * SLAB];
__device__ float g_k[7 * SLAB];
__device__ float g_v[7 * SLAB];
__device__ float g_ctx[7 * SLAB];
__device__ float g_u[7 * SLAB];
__device__ float g_other[SLAB];

__constant__ int c_win[7] = {128, 64, 32, 16, 16, 8, 4};

struct BandPtrs { const float* p[7]; };

// ---------------------------------------------------------------------------
// tf32 MMA GEMM: 128x128 CTA tile, BK=16, 256 threads (8 warps).
// Warp grid 2(m) x 4(n); warp tile 64x32 = 4x4 m16n8k8 HMMA per k8-step.
// C[m,e] = sum_k A[m,k] * W[e,k] + bias[e]   (torch Linear; W row-major [N,K])
// GATE: A = concat(X,U) along K (512); epilogue out = X + sigmoid(C+bias)*U.
// ---------------------------------------------------------------------------

#define SROW 136   // smem row stride: (t*136 + g) % 32 = 8t+g -> conflict-free frag loads

__device__ __forceinline__ void mma_tf32(float4& d, const uint32_t a[4], const uint32_t b[2]) {
    asm volatile(
        "mma.sync.aligned.m16n8k8.row.col.f32.tf32.tf32.f32 "
        "{%0,%1,%2,%3}, {%4,%5,%6,%7}, {%8,%9}, {%0,%1,%2,%3};"
        : "+f"(d.x), "+f"(d.y), "+f"(d.z), "+f"(d.w)
        : "r"(a[0]), "r"(a[1]), "r"(a[2]), "r"(a[3]), "r"(b[0]), "r"(b[1]));
}

template<bool GATE>
__device__ __forceinline__ void mma_gemm_body(
    const float* __restrict__ AX,
    const float* __restrict__ AU,
    const float* __restrict__ W, int ldw,
    const float* __restrict__ bias,
    float* __restrict__ C)
{
    const int NKT = GATE ? 32 : 16;           // number of BK=16 tiles
    __shared__ float As[2][16][SROW];
    __shared__ float Bs[2][16][SROW];

    const int tid  = threadIdx.x;
    const int wid  = tid >> 5;
    const int lane = tid & 31;
    const int g    = lane >> 2;               // 0..7
    const int t    = lane & 3;                // 0..3
    const int m0   = (wid & 1) * 64;          // warp m offset in tile
    const int n0   = (wid >> 1) * 32;         // warp n offset in tile
    const int lm   = tid >> 2;                // loader row 0..63
    const int lk4  = tid & 3;                 // loader k-float4
    const int row0 = blockIdx.x * 128;
    const int col0 = blockIdx.y * 128;

    float4 acc[4][4];
#pragma unroll
    for (int mt = 0; mt < 4; mt++)
#pragma unroll
        for (int nt = 0; nt < 4; nt++) acc[mt][nt] = make_float4(0.f, 0.f, 0.f, 0.f);

    // ---- load tile 0 into stage 0 ----
    {
        float4 a0 = *(const float4*)&AX[(size_t)(row0 + lm) * 256 + lk4 * 4];
        float4 a1 = *(const float4*)&AX[(size_t)(row0 + lm + 64) * 256 + lk4 * 4];
        float4 w0 = *(const float4*)&W[(size_t)(col0 + lm) * ldw + lk4 * 4];
        float4 w1 = *(const float4*)&W[(size_t)(col0 + lm + 64) * ldw + lk4 * 4];
        int kb = lk4 * 4;
        As[0][kb + 0][lm] = a0.x; As[0][kb + 1][lm] = a0.y;
        As[0][kb + 2][lm] = a0.z; As[0][kb + 3][lm] = a0.w;
        As[0][kb + 0][lm + 64] = a1.x; As[0][kb + 1][lm + 64] = a1.y;
        As[0][kb + 2][lm + 64] = a1.z; As[0][kb + 3][lm + 64] = a1.w;
        Bs[0][kb + 0][lm] = w0.x; Bs[0][kb + 1][lm] = w0.y;
        Bs[0][kb + 2][lm] = w0.z; Bs[0][kb + 3][lm] = w0.w;
        Bs[0][kb + 0][lm + 64] = w1.x; Bs[0][kb + 1][lm + 64] = w1.y;
        Bs[0][kb + 2][lm + 64] = w1.z; Bs[0][kb + 3][lm + 64] = w1.w;
    }
    __syncthreads();

    for (int kt = 0; kt < NKT; kt++) {
        const int cs = kt & 1;
        float4 a0n, a1n, w0n, w1n;
        const bool has_next = (kt + 1) < NKT;
        if (has_next) {
            int kn = (kt + 1) * 16;
            const float* Ab; int kloc;
            if (GATE && kn >= 256) { Ab = AU; kloc = kn - 256; }
            else                   { Ab = AX; kloc = kn; }
            a0n = *(const float4*)&Ab[(size_t)(row0 + lm) * 256 + kloc + lk4 * 4];
            a1n = *(const float4*)&Ab[(size_t)(row0 + lm + 64) * 256 + kloc + lk4 * 4];
            w0n = *(const float4*)&W[(size_t)(col0 + lm) * ldw + kn + lk4 * 4];
            w1n = *(const float4*)&W[(size_t)(col0 + lm + 64) * ldw + kn + lk4 * 4];
        }

        // ---- tensor-core micro kernel on stage cs ----
#pragma unroll
        for (int ks = 0; ks < 2; ks++) {
            const int k8 = ks * 8;
            uint32_t af[4][4];
#pragma unroll
            for (int mt = 0; mt < 4; mt++) {
                int m = m0 + mt * 16;
                af[mt][0] = __float_as_uint(As[cs][k8 + t][m + g]);
                af[mt][1] = __float_as_uint(As[cs][k8 + t][m + g + 8]);
                af[mt][2] = __float_as_uint(As[cs][k8 + t + 4][m + g]);
                af[mt][3] = __float_as_uint(As[cs][k8 + t + 4][m + g + 8]);
            }
            uint32_t bf[4][2];
#pragma unroll
            for (int nt = 0; nt < 4; nt++) {
                int n = n0 + nt * 8;
                bf[nt][0] = __float_as_uint(Bs[cs][k8 + t][n + g]);
                bf[nt][1] = __float_as_uint(Bs[cs][k8 + t + 4][n + g]);
            }
#pragma unroll
            for (int mt = 0; mt < 4; mt++)
#pragma unroll
                for (int nt = 0; nt < 4; nt++)
                    mma_tf32(acc[mt][nt], af[mt], bf[nt]);
        }

        if (has_next) {
            const int ns = cs ^ 1;
            __syncthreads();
            int kb = lk4 * 4;
            As[ns][kb + 0][lm] = a0n.x; As[ns][kb + 1][lm] = a0n.y;
            As[ns][kb + 2][lm] = a0n.z; As[ns][kb + 3][lm] = a0n.w;
            As[ns][kb + 0][lm + 64] = a1n.x; As[ns][kb + 1][lm + 64] = a1n.y;
            As[ns][kb + 2][lm + 64] = a1n.z; As[ns][kb + 3][lm + 64] = a1n.w;
            Bs[ns][kb + 0][lm] = w0n.x; Bs[ns][kb + 1][lm] = w0n.y;
            Bs[ns][kb + 2][lm] = w0n.z; Bs[ns][kb + 3][lm] = w0n.w;
            Bs[ns][kb + 0][lm + 64] = w1n.x; Bs[ns][kb + 1][lm + 64] = w1n.y;
            Bs[ns][kb + 2][lm + 64] = w1n.z; Bs[ns][kb + 3][lm + 64] = w1n.w;
            __syncthreads();
        }
    }

    // ---- epilogue: acc[mt][nt] -> rows {m0+mt*16+g, +8}, cols {n0+nt*8+2t, +1}
#pragma unroll
    for (int nt = 0; nt < 4; nt++) {
        int col = col0 + n0 + nt * 8 + 2 * t;
        float bx = bias[col], by = bias[col + 1];
#pragma unroll
        for (int mt = 0; mt < 4; mt++) {
            int r0 = row0 + m0 + mt * 16 + g;
            int r1 = r0 + 8;
            float4 a = acc[mt][nt];
            float v0x = a.x + bx, v0y = a.y + by;   // row r0
            float v1x = a.z + bx, v1y = a.w + by;   // row r1
            size_t o0 = (size_t)r0 * 256 + col;
            size_t o1 = (size_t)r1 * 256 + col;
            if (!GATE) {
                *(float2*)&C[o0] = make_float2(v0x, v0y);
                *(float2*)&C[o1] = make_float2(v1x, v1y);
            } else {
                float2 x0 = *(const float2*)&AX[o0];
                float2 x1 = *(const float2*)&AX[o1];
                float2 u0 = *(const float2*)&AU[o0];
                float2 u1 = *(const float2*)&AU[o1];
                float2 w0, w1;
                w0.x = x0.x + u0.x / (1.f + __expf(-v0x));
                w0.y = x0.y + u0.y / (1.f + __expf(-v0y));
                w1.x = x1.x + u1.x / (1.f + __expf(-v1x));
                w1.y = x1.y + u1.y / (1.f + __expf(-v1y));
                *(float2*)&C[o0] = w0;
                *(float2*)&C[o1] = w1;
            }
        }
    }
}

// ---------------- K1: QKV projections (z = band*3 + {q,k,v}) ----------------
__global__ void __launch_bounds__(256)
qkv_gemm(BandPtrs bp,
         const float* __restrict__ qw, const float* __restrict__ qb,
         const float* __restrict__ kw, const float* __restrict__ kb,
         const float* __restrict__ vw, const float* __restrict__ vb)
{
    int z = blockIdx.z;
    int n = z / 3, which = z - 3 * n;
    const float* A = bp.p[n];
    const float* W; const float* bias; float* C;
    if (which == 0)      { W = qw + (size_t)n * 65536; bias = qb + n * 256; C = g_q + (size_t)n * SLAB; }
    else if (which == 1) { W = kw + (size_t)n * 65536; bias = kb + n * 256; C = g_k + (size_t)n * SLAB; }
    else                 { W = vw + (size_t)n * 65536; bias = vb + n * 256; C = g_v + (size_t)n * SLAB; }
    mma_gemm_body<false>(A, nullptr, W, 256, bias, C);
}

// ---------------- K2: windowed attention, warp per query --------------------
__global__ void attn_kernel()
{
    int warp = (blockIdx.x * blockDim.x + threadIdx.x) >> 5;
    int lane = threadIdx.x & 31;
    if (warp >= 7 * M_ROWS) return;
    int n  = warp / M_ROWS;
    int tf = warp - n * M_ROWS;
    int b  = tf >> 10;
    int t  = tf & 1023;
    int w  = c_win[n];

    const float4* qrow = (const float4*)(g_q + ((size_t)n * M_ROWS + tf) * 256);
    float4 q0 = qrow[lane];
    float4 q1 = qrow[lane + 32];

    int j0 = t - w + 1; if (j0 < 0) j0 = 0;
    int cnt = t - j0 + 1;

    const float4* kbase = (const float4*)(g_k + ((size_t)n * M_ROWS + (size_t)b * 1024 + j0) * 256);
    float sc[4];

    for (int jj = 0; jj < cnt; jj++) {
        const float4* kr = kbase + (size_t)jj * 64;
        float4 k0 = kr[lane];
        float4 k1 = kr[lane + 32];
        float p = q0.x * k0.x + q0.y * k0.y + q0.z * k0.z + q0.w * k0.w
                + q1.x * k1.x + q1.y * k1.y + q1.z * k1.z + q1.w * k1.w;
#pragma unroll
        for (int off = 16; off > 0; off >>= 1)
            p += __shfl_xor_sync(0xffffffffu, p, off);
        if ((jj & 31) == lane) sc[jj >> 5] = p;
    }

    const float scale = 0.0625f;
    float mx = -1e30f;
#pragma unroll
    for (int s = 0; s < 4; s++) {
        int jj = s * 32 + lane;
        if (jj < cnt) mx = fmaxf(mx, sc[s] * scale);
    }
#pragma unroll
    for (int off = 16; off > 0; off >>= 1)
        mx = fmaxf(mx, __shfl_xor_sync(0xffffffffu, mx, off));

    float sum = 0.f;
#pragma unroll
    for (int s = 0; s < 4; s++) {
        int jj = s * 32 + lane;
        float e = (jj < cnt) ? expf(sc[s] * scale - mx) : 0.f;
        sc[s] = e;
        sum += e;
    }
#pragma unroll
    for (int off = 16; off > 0; off >>= 1)
        sum += __shfl_xor_sync(0xffffffffu, sum, off);
    float inv = 1.f / sum;

    float4 acc0 = {0.f, 0.f, 0.f, 0.f};
    float4 acc1 = {0.f, 0.f, 0.f, 0.f};
    const float4* vbase = (const float4*)(g_v + ((size_t)n * M_ROWS + (size_t)b * 1024 + j0) * 256);
    for (int jj = 0; jj < cnt; jj++) {
        float p = __shfl_sync(0xffffffffu, sc[jj >> 5], jj & 31);
        const float4* vr = vbase + (size_t)jj * 64;
        float4 v0 = vr[lane];
        float4 v1 = vr[lane + 32];
        acc0.x += p * v0.x; acc0.y += p * v0.y; acc0.z += p * v0.z; acc0.w += p * v0.w;
        acc1.x += p * v1.x; acc1.y += p * v1.y; acc1.z += p * v1.z; acc1.w += p * v1.w;
    }

    float4* crow = (float4*)(g_ctx + ((size_t)n * M_ROWS + tf) * 256);
    acc0.x *= inv; acc0.y *= inv; acc0.z *= inv; acc0.w *= inv;
    acc1.x *= inv; acc1.y *= inv; acc1.z *= inv; acc1.w *= inv;
    crow[lane]      = acc0;
    crow[lane + 32] = acc1;
}

// ---------------- K3: other = mean of ctx over bands != 3 -------------------
__global__ void other_kernel()
{
    int i = blockIdx.x * blockDim.x + threadIdx.x;
    if (i >= SLAB / 4) return;
    const float4* c = (const float4*)g_ctx;
    float4 s = {0.f, 0.f, 0.f, 0.f};
#pragma unroll
    for (int nn = 0; nn < 7; nn++) {
        if (nn == 3) continue;
        float4 v = c[(size_t)nn * (SLAB / 4) + i];
        s.x += v.x; s.y += v.y; s.z += v.z; s.w += v.w;
    }
    const float k = 1.f / 6.f;
    s.x *= k; s.y *= k; s.z *= k; s.w *= k;
    ((float4*)g_other)[i] = s;
}

// ---------------- K4: per-band update projections u[n] ----------------------
__global__ void __launch_bounds__(256)
u_gemm(const float* __restrict__ crossw,  const float* __restrict__ crossb,
       const float* __restrict__ crossrw, const float* __restrict__ crossrb,
       const float* __restrict__ bridgew, const float* __restrict__ bridgeb)
{
    int n = blockIdx.z;
    const float *A, *W, *bias;
    switch (n) {
        case 0:  A = g_ctx + (size_t)6 * SLAB; W = crossrw;             bias = crossrb;       break;
        case 1:  A = g_ctx + (size_t)5 * SLAB; W = crossrw + 65536;     bias = crossrb + 256; break;
        case 2:  A = g_ctx + (size_t)4 * SLAB; W = crossrw + 2 * 65536; bias = crossrb + 512; break;
        case 3:  A = g_other;                  W = bridgew;             bias = bridgeb;       break;
        case 4:  A = g_ctx + (size_t)2 * SLAB; W = crossw + 2 * 65536;  bias = crossb + 512;  break;
        case 5:  A = g_ctx + (size_t)1 * SLAB; W = crossw + 65536;      bias = crossb + 256;  break;
        default: A = g_ctx;                    W = crossw;              bias = crossb;        break;
    }
    mma_gemm_body<false>(A, nullptr, W, 256, bias, g_u + (size_t)n * SLAB);
}

// ---------------- K5: gate GEMM (K=512) + sigmoid + residual ----------------
__global__ void __launch_bounds__(256)
gate_gemm(BandPtrs bp, const float* __restrict__ gatew,
          const float* __restrict__ gateb, float* __restrict__ out)
{
    int n = blockIdx.z;
    mma_gemm_body<true>(bp.p[n], g_u + (size_t)n * SLAB,
                        gatew + (size_t)n * 256 * 512, 512,
                        gateb + n * 256, out + (size_t)n * SLAB);
}

// ---------------------------------------------------------------------------
extern "C" void kernel_launch(void* const* d_in, const int* in_sizes, int n_in,
                              void* d_out, int out_size)
{
    BandPtrs bp;
    for (int i = 0; i < 7; i++) bp.p[i] = (const float*)d_in[i];
    const float* qw      = (const float*)d_in[7];
    const float* qb      = (const float*)d_in[8];
    const float* kw      = (const float*)d_in[9];
    const float* kb      = (const float*)d_in[10];
    const float* vw      = (const float*)d_in[11];
    const float* vb      = (const float*)d_in[12];
    const float* crossw  = (const float*)d_in[13];
    const float* crossb  = (const float*)d_in[14];
    const float* crossrw = (const float*)d_in[15];
    const float* crossrb = (const float*)d_in[16];
    const float* gatew   = (const float*)d_in[17];
    const float* gateb   = (const float*)d_in[18];
    const float* bridgew = (const float*)d_in[19];
    const float* bridgeb = (const float*)d_in[20];
    float* out = (float*)d_out;

    qkv_gemm<<<dim3(M_ROWS / 128, D_DIM / 128, 21), 256>>>(bp, qw, qb, kw, kb, vw, vb);
    attn_kernel<<<(7 * M_ROWS) / 8, 256>>>();
    other_kernel<<<(SLAB / 4) / 256, 256>>>();
    u_gemm<<<dim3(M_ROWS / 128, D_DIM / 128, 7), 256>>>(crossw, crossb, crossrw, crossrb,
                                                        bridgew, bridgeb);
    gate_gemm<<<dim3(M_ROWS / 128, D_DIM / 128, 7), 256>>>(bp, gatew, gateb, out);
}